// round 15
// baseline (speedup 1.0000x reference)
#include <cuda_runtime.h>
#include <cuda_bf16.h>
#include <math.h>
#include <stdint.h>

#define BSZ   64
#define SEQ   197
#define CDIM  768
#define NH    12
#define HD    64
#define KEEP  160
#define SCALEF 0.125f

#define BH   (BSZ*NH)
#define TOK  (BSZ*SEQ)

#define SEQP   228   /* global V^T pitch (u32 elems) */

/* ---------------- scratch (device globals; no allocs allowed) ------ */
__device__ __nv_bfloat16 g_qh[BH*SEQ*HD], g_ql[BH*SEQ*HD];
__device__ __nv_bfloat16 g_kh[BH*SEQ*HD], g_kl[BH*SEQ*HD];
__device__ uint32_t      g_vt[BH*HD*SEQP];

__device__ __nv_bfloat16 g_xh[TOK*CDIM],  g_xl[TOK*CDIM];
__device__ __nv_bfloat16 g_wqh[3*CDIM*CDIM], g_wql[3*CDIM*CDIM];
__device__ __nv_bfloat16 g_wph[CDIM*CDIM],   g_wpl[CDIM*CDIM];
__device__ __nv_bfloat16 g_cth[TOK*CDIM], g_ctl[TOK*CDIM];

/* top-k staging */
__device__ float g_qc[BSZ*CDIM];
__device__ float g_u [BSZ*NH*CDIM];
__device__ float g_wt[BSZ*SEQ];

/* ---------------- helpers ------------------------------------------ */
__device__ __forceinline__ uint32_t pack_hi_lo(float v0, float v1, uint32_t* lo)
{
    __nv_bfloat16 h0 = __float2bfloat16(v0);
    __nv_bfloat16 h1 = __float2bfloat16(v1);
    __nv_bfloat16 l0 = __float2bfloat16(v0 - __bfloat162float(h0));
    __nv_bfloat16 l1 = __float2bfloat16(v1 - __bfloat162float(h1));
    uint32_t hi = ((uint32_t)__bfloat16_as_ushort(h1) << 16) | __bfloat16_as_ushort(h0);
    *lo         = ((uint32_t)__bfloat16_as_ushort(l1) << 16) | __bfloat16_as_ushort(l0);
    return hi;
}
__device__ __forceinline__ uint32_t pack_v(float v)
{
    __nv_bfloat16 h = __float2bfloat16(v);
    __nv_bfloat16 l = __float2bfloat16(v - __bfloat162float(h));
    return (uint32_t)__bfloat16_as_ushort(h) | ((uint32_t)__bfloat16_as_ushort(l) << 16);
}

#define CP_ASYNC16(dst, src) \
    asm volatile("cp.async.cg.shared.global [%0], [%1], 16;" :: "r"(dst), "l"(src))
#define CP_COMMIT() asm volatile("cp.async.commit_group;" ::: "memory")
#define CP_WAIT(n)  asm volatile("cp.async.wait_group %0;" :: "n"(n) : "memory")

__device__ __forceinline__ void ldsm4(uint32_t* r, const void* p)
{
    uint32_t a = (uint32_t)__cvta_generic_to_shared(p);
    asm volatile("ldmatrix.sync.aligned.m8n8.x4.shared.b16 {%0,%1,%2,%3}, [%4];"
                 : "=r"(r[0]), "=r"(r[1]), "=r"(r[2]), "=r"(r[3]) : "r"(a));
}

/* ---------------- merged split fp32 -> bf16 hi/lo ------------------ */
#define NX  (TOK*CDIM)
#define NWQ (3*CDIM*CDIM)
#define NWP (CDIM*CDIM)
#define NSPLIT (NX + NWQ + NWP)

__global__ void split_all_kernel(const float* __restrict__ x,
                                 const float* __restrict__ wq,
                                 const float* __restrict__ wp)
{
    int i = blockIdx.x * 256 + threadIdx.x;
    if (i >= NSPLIT) return;
    const float* s;
    __nv_bfloat16 *hi, *lo;
    int j;
    if (i < NX)            { s = x;  hi = g_xh;  lo = g_xl;  j = i; }
    else if (i < NX + NWQ) { s = wq; hi = g_wqh; lo = g_wql; j = i - NX; }
    else                   { s = wp; hi = g_wph; lo = g_wpl; j = i - NX - NWQ; }
    float v = s[j];
    __nv_bfloat16 h = __float2bfloat16(v);
    hi[j] = h;
    lo[j] = __float2bfloat16(v - __bfloat162float(h));
}

/* ---------------- HMMA GEMM: 256x128 CTA tile ---------------------- */
#define MT 256
#define NT 128
#define KPAN 32
#define SPAD 40
#define TILEA  (256*SPAD*2)                 /* 20480 B */
#define TILEB2 (128*SPAD*2)                 /* 10240 B */
#define STAGEB (2*TILEA + 2*TILEB2)         /* 61440 B */
#define GEMM_SMEM (2*STAGEB)                /* 122880 B */

__device__ __forceinline__ void mma16816(float* c, const uint32_t* a,
                                         uint32_t b0, uint32_t b1)
{
    asm volatile(
        "mma.sync.aligned.m16n8k16.row.col.f32.bf16.bf16.f32 "
        "{%0,%1,%2,%3}, {%4,%5,%6,%7}, {%8,%9}, {%0,%1,%2,%3};"
        : "+f"(c[0]), "+f"(c[1]), "+f"(c[2]), "+f"(c[3])
        : "r"(a[0]), "r"(a[1]), "r"(a[2]), "r"(a[3]), "r"(b0), "r"(b1));
}

/* stage 256 rows x 32 cols (A) */
__device__ __forceinline__ void stage_asyncA(uint32_t sbase,
        const __nv_bfloat16* __restrict__ g, int row0, int rowmax, int kb, int t)
{
#pragma unroll
    for (int i = 0; i < 4; i++) {
        const int idx = t + i * 256;
        const int row = idx >> 2;
        const int c8  = (idx & 3) * 8;
        int gr = row0 + row; if (gr > rowmax) gr = rowmax;
        CP_ASYNC16(sbase + (uint32_t)(row * SPAD + c8) * 2,
                   g + (size_t)gr * CDIM + kb + c8);
    }
}
/* stage 128 rows x 32 cols (B) */
__device__ __forceinline__ void stage_asyncB(uint32_t sbase,
        const __nv_bfloat16* __restrict__ g, int row0, int rowmax, int kb, int t)
{
#pragma unroll
    for (int i = 0; i < 2; i++) {
        const int idx = t + i * 256;
        const int row = idx >> 2;
        const int c8  = (idx & 3) * 8;
        int gr = row0 + row; if (gr > rowmax) gr = rowmax;
        CP_ASYNC16(sbase + (uint32_t)(row * SPAD + c8) * 2,
                   g + (size_t)gr * CDIM + kb + c8);
    }
}

__global__ __launch_bounds__(256, 1) void hmma_gemm(int mode,
        const float* __restrict__ bias, float* __restrict__ outp)
{
    extern __shared__ __align__(16) char dynsm[];
    const uint32_t sb = (uint32_t)__cvta_generic_to_shared(dynsm);

    const int t    = threadIdx.x;
    const int wid  = t >> 5, lane = t & 31;
    const int gq   = lane >> 2, tig = lane & 3;
    const int wm   = (wid & 3) * 64;     /* 4 m-warps x 64 rows */
    const int wn   = (wid >> 2) * 64;    /* 2 n-warps x 64 cols */
    const int m0   = blockIdx.y * MT;
    const int n0   = blockIdx.x * NT;
    const int lrA  = lane & 15;
    const int lcA  = (lane >> 4) << 3;
    const int lrB  = ((lane >> 4) << 3) | (lane & 7);
    const int lcB  = lane & 8;

    const __nv_bfloat16 *Ah, *Al, *Bh, *Bl;
    int brmax;
    if (mode == 0) { Ah = g_xh;  Al = g_xl;  Bh = g_wqh; Bl = g_wql; brmax = 3*CDIM - 1; }
    else           { Ah = g_cth; Al = g_ctl; Bh = g_wph; Bl = g_wpl; brmax = CDIM - 1;   }

    float acc[4][8][4];
#pragma unroll
    for (int mi = 0; mi < 4; mi++)
#pragma unroll
        for (int ni = 0; ni < 8; ni++)
#pragma unroll
            for (int r = 0; r < 4; r++) acc[mi][ni][r] = 0.f;

    stage_asyncA(sb + 0,                 Ah, m0, TOK - 1, 0, t);
    stage_asyncA(sb + TILEA,             Al, m0, TOK - 1, 0, t);
    stage_asyncB(sb + 2*TILEA,           Bh, n0, brmax,   0, t);
    stage_asyncB(sb + 2*TILEA + TILEB2,  Bl, n0, brmax,   0, t);
    CP_COMMIT();

    const int NP = CDIM / KPAN;
    for (int p = 0; p < NP; p++) {
        if (p + 1 < NP) {
            const uint32_t nb = sb + ((p + 1) & 1) * STAGEB;
            const int kb = (p + 1) * KPAN;
            stage_asyncA(nb + 0,                Ah, m0, TOK - 1, kb, t);
            stage_asyncA(nb + TILEA,            Al, m0, TOK - 1, kb, t);
            stage_asyncB(nb + 2*TILEA,          Bh, n0, brmax,   kb, t);
            stage_asyncB(nb + 2*TILEA + TILEB2, Bl, n0, brmax,   kb, t);
            CP_COMMIT();
            CP_WAIT(1);
        } else {
            CP_WAIT(0);
        }
        __syncthreads();

        const char* cbuf = dynsm + (p & 1) * STAGEB;
        const __nv_bfloat16* sAh = (const __nv_bfloat16*)(cbuf);
        const __nv_bfloat16* sAl = (const __nv_bfloat16*)(cbuf + TILEA);
        const __nv_bfloat16* sBh = (const __nv_bfloat16*)(cbuf + 2*TILEA);
        const __nv_bfloat16* sBl = (const __nv_bfloat16*)(cbuf + 2*TILEA + TILEB2);

#pragma unroll
        for (int ks = 0; ks < 2; ks++) {
            const int ko = ks * 16;
            uint32_t ah[4][4], al[4][4];
#pragma unroll
            for (int mi = 0; mi < 4; mi++) {
                ldsm4(ah[mi], &sAh[(wm + mi * 16 + lrA) * SPAD + ko + lcA]);
                ldsm4(al[mi], &sAl[(wm + mi * 16 + lrA) * SPAD + ko + lcA]);
            }
#pragma unroll
            for (int ni2 = 0; ni2 < 4; ni2++) {
                uint32_t bh4[4], bl4[4];
                ldsm4(bh4, &sBh[(wn + ni2 * 16 + lrB) * SPAD + ko + lcB]);
                ldsm4(bl4, &sBl[(wn + ni2 * 16 + lrB) * SPAD + ko + lcB]);
#pragma unroll
                for (int mi = 0; mi < 4; mi++) {
                    mma16816(acc[mi][2*ni2    ], ah[mi], bh4[0], bh4[1]);
                    mma16816(acc[mi][2*ni2    ], ah[mi], bl4[0], bl4[1]);
                    mma16816(acc[mi][2*ni2    ], al[mi], bh4[0], bh4[1]);
                    mma16816(acc[mi][2*ni2 + 1], ah[mi], bh4[2], bh4[3]);
                    mma16816(acc[mi][2*ni2 + 1], ah[mi], bl4[2], bl4[3]);
                    mma16816(acc[mi][2*ni2 + 1], al[mi], bh4[2], bh4[3]);
                }
            }
        }
        __syncthreads();
    }

#pragma unroll
    for (int mi = 0; mi < 4; mi++) {
#pragma unroll
        for (int h2 = 0; h2 < 2; h2++) {
            const int m = m0 + wm + mi * 16 + gq + h2 * 8;
            if (m >= TOK) continue;
#pragma unroll
            for (int ni = 0; ni < 8; ni++) {
                const int col = n0 + wn + ni * 8 + 2 * tig;
                const float v0 = acc[mi][ni][h2 * 2 + 0];
                const float v1 = acc[mi][ni][h2 * 2 + 1];
                if (mode == 1) {
                    float2 o = make_float2(v0 + bias[col], v1 + bias[col + 1]);
                    *reinterpret_cast<float2*>(&outp[(size_t)m * CDIM + col]) = o;
                } else {
                    const int s  = col / CDIM;
                    const int rm = col % CDIM;
                    const int h  = rm / HD, dd = rm % HD;
                    const int bidx = m / SEQ, n = m % SEQ;
                    if (s == 2) {
                        const size_t vo = ((size_t)(bidx * NH + h) * HD + dd) * SEQP + n;
                        g_vt[vo]        = pack_v(v0);
                        g_vt[vo + SEQP] = pack_v(v1);
                    } else {
                        const size_t off = ((size_t)(bidx * NH + h) * SEQ + n) * HD + dd;
                        uint32_t lo, hi = pack_hi_lo(v0, v1, &lo);
                        __nv_bfloat16 *dh = (s == 0) ? g_qh : g_kh;
                        __nv_bfloat16 *dl = (s == 0) ? g_ql : g_kl;
                        *reinterpret_cast<uint32_t*>(&dh[off]) = hi;
                        *reinterpret_cast<uint32_t*>(&dl[off]) = lo;
                    }
                }
            }
        }
    }
}

/* ---------------- fused scores + softmax + PV (persistent per bh) --
   block = bh. K/V staged ONCE; loop over 4 Q-tiles of 64 rows.       */
#define FPITCH 232
#define QPITCH 72
#define SP_OFF 0
#define Q_OFF  59392
#define K_OFF  77824
#define V_OFF  151552
#define FSMEM  210944

__global__ __launch_bounds__(256, 1) void fused_attn()
{
    extern __shared__ __align__(16) char fsm[];
    float*         S  = (float*)(fsm + SP_OFF);
    __nv_bfloat16* Ph = (__nv_bfloat16*)(fsm + SP_OFF);
    __nv_bfloat16* Pl = (__nv_bfloat16*)(fsm + SP_OFF + 64*FPITCH*2);
    __nv_bfloat16* Qh = (__nv_bfloat16*)(fsm + Q_OFF);
    __nv_bfloat16* Ql = Qh + 64*QPITCH;
    __nv_bfloat16* Kh = (__nv_bfloat16*)(fsm + K_OFF);
    __nv_bfloat16* Kl = Kh + 256*QPITCH;
    __nv_bfloat16* Vh = (__nv_bfloat16*)(fsm + V_OFF);
    __nv_bfloat16* Vl = Vh + 64*FPITCH;

    const int bh   = blockIdx.x;
    const int b    = bh / NH, h = bh % NH;
    const int t    = threadIdx.x;
    const int lane = t & 31;
    const int w    = t >> 5;
    const int gq   = lane >> 2, tig = lane & 3;
    const int lrA  = lane & 15;
    const int lcA  = (lane >> 4) << 3;
    const int lrB  = ((lane >> 4) << 3) | (lane & 7);
    const int lcB  = lane & 8;

    const size_t base = (size_t)bh * SEQ * HD;

    /* stage K once */
#pragma unroll
    for (int i = 0; i < 8; i++) {
        const int idx = t + i * 256;
        const int row = idx >> 3;
        const int c8  = (idx & 7) * 8;
        int gr = row; if (gr > SEQ - 1) gr = SEQ - 1;
        *reinterpret_cast<uint4*>(&Kh[row * QPITCH + c8]) =
            *reinterpret_cast<const uint4*>(&g_kh[base + (size_t)gr * HD + c8]);
        *reinterpret_cast<uint4*>(&Kl[row * QPITCH + c8]) =
            *reinterpret_cast<const uint4*>(&g_kl[base + (size_t)gr * HD + c8]);
    }
    /* stage V^T once */
    const uint32_t* vt = g_vt + (size_t)bh * HD * SEQP;
#pragma unroll
    for (int dd = 0; dd < 8; dd++) {
        const int d = w * 8 + dd;
#pragma unroll
        for (int i = 0; i < 8; i++) {
            const int n = lane + i * 32;
            if (n < FPITCH) {
                uint32_t p = (n < SEQP) ? vt[d * SEQP + n] : 0u;
                Vh[d * FPITCH + n] = __ushort_as_bfloat16((unsigned short)(p & 0xffffu));
                Vl[d * FPITCH + n] = __ushort_as_bfloat16((unsigned short)(p >> 16));
            }
        }
    }

    for (int qt = 0; qt < 4; qt++) {
        const int q0 = qt * 64;

#pragma unroll
        for (int i = 0; i < 2; i++) {
            const int idx = t + i * 256;
            const int row = idx >> 3;
            const int c8  = (idx & 7) * 8;
            int gr = q0 + row; if (gr > SEQ - 1) gr = SEQ - 1;
            *reinterpret_cast<uint4*>(&Qh[row * QPITCH + c8]) =
                *reinterpret_cast<const uint4*>(&g_qh[base + (size_t)gr * HD + c8]);
            *reinterpret_cast<uint4*>(&Ql[row * QPITCH + c8]) =
                *reinterpret_cast<const uint4*>(&g_ql[base + (size_t)gr * HD + c8]);
        }
        __syncthreads();

        /* phase 1: S = Q K^T */
        {
            const int wm = (w & 1) * 32;
            const int wn = (w >> 1) * 64;
            float sacc[2][8][4];
#pragma unroll
            for (int mi = 0; mi < 2; mi++)
#pragma unroll
                for (int ni = 0; ni < 8; ni++)
#pragma unroll
                    for (int r = 0; r < 4; r++) sacc[mi][ni][r] = 0.f;

#pragma unroll
            for (int ks = 0; ks < 4; ks++) {
                const int ko = ks * 16;
                uint32_t ah[2][4], al[2][4];
#pragma unroll
                for (int mi = 0; mi < 2; mi++) {
                    ldsm4(ah[mi], &Qh[(wm + mi * 16 + lrA) * QPITCH + ko + lcA]);
                    ldsm4(al[mi], &Ql[(wm + mi * 16 + lrA) * QPITCH + ko + lcA]);
                }
#pragma unroll
                for (int ni2 = 0; ni2 < 4; ni2++) {
                    uint32_t bh4[4], bl4[4];
                    ldsm4(bh4, &Kh[(wn + ni2 * 16 + lrB) * QPITCH + ko + lcB]);
                    ldsm4(bl4, &Kl[(wn + ni2 * 16 + lrB) * QPITCH + ko + lcB]);
#pragma unroll
                    for (int mi = 0; mi < 2; mi++) {
                        mma16816(sacc[mi][2*ni2    ], ah[mi], bh4[0], bh4[1]);
                        mma16816(sacc[mi][2*ni2    ], ah[mi], bl4[0], bl4[1]);
                        mma16816(sacc[mi][2*ni2    ], al[mi], bh4[0], bh4[1]);
                        mma16816(sacc[mi][2*ni2 + 1], ah[mi], bh4[2], bh4[3]);
                        mma16816(sacc[mi][2*ni2 + 1], ah[mi], bl4[2], bl4[3]);
                        mma16816(sacc[mi][2*ni2 + 1], al[mi], bh4[2], bh4[3]);
                    }
                }
            }
#pragma unroll
            for (int mi = 0; mi < 2; mi++)
#pragma unroll
                for (int h2 = 0; h2 < 2; h2++) {
                    const int row = wm + mi * 16 + gq + h2 * 8;
#pragma unroll
                    for (int ni = 0; ni < 8; ni++) {
                        const int col = wn + ni * 8 + 2 * tig;
                        if (col + 1 < FPITCH) {
                            S[row * FPITCH + col]     = sacc[mi][ni][h2*2+0] * SCALEF;
                            S[row * FPITCH + col + 1] = sacc[mi][ni][h2*2+1] * SCALEF;
                        }
                    }
                }
        }
        __syncthreads();

        /* phase 2: softmax */
        float pv[8][8];
#pragma unroll
        for (int r8 = 0; r8 < 8; r8++) {
            const int sr = w * 8 + r8;
            float mx = -1e30f;
#pragma unroll
            for (int i = 0; i < 8; i++) {
                const int c = lane + i * 32;
                float v = (c < SEQ) ? S[sr * FPITCH + c] : -1e30f;
                pv[r8][i] = v;
                mx = fmaxf(mx, v);
            }
#pragma unroll
            for (int off = 16; off > 0; off >>= 1)
                mx = fmaxf(mx, __shfl_xor_sync(0xffffffffu, mx, off));
            float s = 0.f;
#pragma unroll
            for (int i = 0; i < 8; i++) {
                const int c = lane + i * 32;
                const float e = (c < SEQ) ? __expf(pv[r8][i] - mx) : 0.f;
                pv[r8][i] = e;
                s += e;
            }
#pragma unroll
            for (int off = 16; off > 0; off >>= 1)
                s += __shfl_xor_sync(0xffffffffu, s, off);
            const float inv = 1.f / s;
#pragma unroll
            for (int i = 0; i < 8; i++) pv[r8][i] *= inv;
        }
        __syncthreads();
#pragma unroll
        for (int r8 = 0; r8 < 8; r8++) {
            const int sr = w * 8 + r8;
#pragma unroll
            for (int i = 0; i < 8; i++) {
                const int c = lane + i * 32;
                if (c < FPITCH) {
                    const float p = pv[r8][i];
                    __nv_bfloat16 ph = __float2bfloat16(p);
                    __nv_bfloat16 pl = __float2bfloat16(p - __bfloat162float(ph));
                    Ph[sr * FPITCH + c] = ph;
                    Pl[sr * FPITCH + c] = pl;
                }
            }
        }
        __syncthreads();

        /* phase 3: ctx = P @ V */
        {
            const int wm = (w & 1) * 32;
            const int wn = (w >> 1) * 16;
            float acc[2][2][4];
#pragma unroll
            for (int mi = 0; mi < 2; mi++)
#pragma unroll
                for (int ni = 0; ni < 2; ni++)
#pragma unroll
                    for (int r = 0; r < 4; r++) acc[mi][ni][r] = 0.f;

#pragma unroll 1
            for (int ks = 0; ks < 13; ks++) {
                const int ko = ks * 16;
                uint32_t ah[2][4], al[2][4];
#pragma unroll
                for (int mi = 0; mi < 2; mi++) {
                    ldsm4(ah[mi], &Ph[(wm + mi * 16 + lrA) * FPITCH + ko + lcA]);
                    ldsm4(al[mi], &Pl[(wm + mi * 16 + lrA) * FPITCH + ko + lcA]);
                }
                uint32_t bh4[4], bl4[4];
                ldsm4(bh4, &Vh[(wn + lrB) * FPITCH + ko + lcB]);
                ldsm4(bl4, &Vl[(wn + lrB) * FPITCH + ko + lcB]);
#pragma unroll
                for (int mi = 0; mi < 2; mi++) {
                    mma16816(acc[mi][0], ah[mi], bh4[0], bh4[1]);
                    mma16816(acc[mi][0], ah[mi], bl4[0], bl4[1]);
                    mma16816(acc[mi][0], al[mi], bh4[0], bh4[1]);
                    mma16816(acc[mi][1], ah[mi], bh4[2], bh4[3]);
                    mma16816(acc[mi][1], ah[mi], bl4[2], bl4[3]);
                    mma16816(acc[mi][1], al[mi], bh4[2], bh4[3]);
                }
            }

#pragma unroll
            for (int mi = 0; mi < 2; mi++)
#pragma unroll
                for (int h2 = 0; h2 < 2; h2++) {
                    const int r = q0 + wm + mi * 16 + gq + h2 * 8;
                    if (r >= SEQ) continue;
#pragma unroll
                    for (int ni = 0; ni < 2; ni++) {
                        const int col = wn + ni * 8 + 2 * tig;
                        const size_t off = (size_t)(b * SEQ + r) * CDIM + h * HD + col;
                        uint32_t lo, hi = pack_hi_lo(acc[mi][ni][h2*2+0], acc[mi][ni][h2*2+1], &lo);
                        *reinterpret_cast<uint32_t*>(&g_cth[off]) = hi;
                        *reinterpret_cast<uint32_t*>(&g_ctl[off]) = lo;
                    }
                }
        }
        __syncthreads();
    }
}

/* ---------------- top-k stages (exact fp32) ------------------------ */
__global__ __launch_bounds__(256) void topk_qc(const float* __restrict__ x,
                                               const float* __restrict__ w)
{
    __shared__ float xc[CDIM];
    const int b  = blockIdx.x;
    const int jt = blockIdx.y;
    const int t  = threadIdx.x;
    const int lane = t & 31, wrp = t >> 5;

    for (int i = t; i < CDIM; i += 256) xc[i] = x[(size_t)(b * SEQ) * CDIM + i];
    __syncthreads();

#pragma unroll
    for (int jj = 0; jj < 8; jj++) {
        const int j = jt * 64 + wrp * 8 + jj;
        const float* wr = w + (size_t)j * CDIM;
        float s = 0.f;
#pragma unroll
        for (int c4 = 0; c4 < 6; c4++) {
            const int c = (c4 * 32 + lane) * 4;
            const float4 wv = *reinterpret_cast<const float4*>(&wr[c]);
            s += wv.x * xc[c] + wv.y * xc[c+1] + wv.z * xc[c+2] + wv.w * xc[c+3];
        }
#pragma unroll
        for (int off = 16; off > 0; off >>= 1)
            s += __shfl_xor_sync(0xffffffffu, s, off);
        if (lane == 0) g_qc[b * CDIM + j] = s;
    }
}

__global__ __launch_bounds__(256) void topk_u(const float* __restrict__ w)
{
    __shared__ float qh[HD];
    const int b = blockIdx.x, h = blockIdx.y;
    const int t = threadIdx.x;
    if (t < HD) qh[t] = g_qc[b * CDIM + h * HD + t];
    __syncthreads();

    const float* wk = w + (size_t)(CDIM + h * HD) * CDIM;
#pragma unroll
    for (int cc = 0; cc < 3; cc++) {
        const int c = cc * 256 + t;
        float s = 0.f;
#pragma unroll 16
        for (int d = 0; d < HD; d++) s += wk[(size_t)d * CDIM + c] * qh[d];
        g_u[((size_t)b * NH + h) * CDIM + c] = s;
    }
}

__global__ __launch_bounds__(256) void topk_wt(const float* __restrict__ x)
{
    const int b = blockIdx.x;
    const int t = threadIdx.x;
    const int lane = t & 31, wrp = t >> 5;
    const int m = blockIdx.y * 8 + wrp;
    if (m >= SEQ) return;

    const float* xr = x + (size_t)(b * SEQ + m) * CDIM;
    float4 xv[6];
#pragma unroll
    for (int c4 = 0; c4 < 6; c4++)
        xv[c4] = *reinterpret_cast<const float4*>(&xr[(c4 * 32 + lane) * 4]);

    const float* ub = g_u + (size_t)b * NH * CDIM;
    float tot = 0.f;
#pragma unroll
    for (int h = 0; h < NH; h++) {
        const float* ur = ub + h * CDIM;
        float s = 0.f;
#pragma unroll
        for (int c4 = 0; c4 < 6; c4++) {
            const int c = (c4 * 32 + lane) * 4;
            const float4 uv = *reinterpret_cast<const float4*>(&ur[c]);
            s += uv.x * xv[c4].x + uv.y * xv[c4].y + uv.z * xv[c4].z + uv.w * xv[c4].w;
        }
#pragma unroll
        for (int off = 16; off > 0; off >>= 1)
            s += __shfl_xor_sync(0xffffffffu, s, off);
        tot += fabsf(s);
    }
    if (lane == 0) g_wt[b * SEQ + m] = tot;
}

__global__ __launch_bounds__(256) void topk_emit(float* __restrict__ out_keep,
                                                 int write_keep)
{
    __shared__ float wt[SEQ];
    __shared__ unsigned char keep[SEQ];
    const int b = blockIdx.x, t = threadIdx.x;

    if (t < SEQ) wt[t] = g_wt[b * SEQ + t];
    __syncthreads();
    if (t < SEQ) {
        const float wi = wt[t];
        int cnt = 0;
        for (int j = 0; j < SEQ; j++) {
            const float wj = wt[j];
            cnt += (wj > wi) || (wj == wi && j < t);
        }
        keep[t] = (cnt < KEEP) ? 1 : 0;
    }
    __syncthreads();
    if (write_keep && t < SEQ && keep[t]) {
        int pos = 0;
        for (int j = 0; j < t; j++) pos += keep[j];
        out_keep[b * KEEP + pos] = (float)t;
    }
}

/* ------------------------------------------------------------------ */
extern "C" void kernel_launch(void* const* d_in, const int* in_sizes, int n_in,
                              void* d_out, int out_size)
{
    const float* x      = (const float*)d_in[0];
    const float* qkv_w  = (const float*)d_in[1];
    const float* proj_w = (const float*)d_in[2];
    const float* proj_b = (const float*)d_in[3];
    float* out = (float*)d_out;

    cudaFuncSetAttribute(hmma_gemm,  cudaFuncAttributeMaxDynamicSharedMemorySize, GEMM_SMEM);
    cudaFuncSetAttribute(fused_attn, cudaFuncAttributeMaxDynamicSharedMemorySize, FSMEM);

    static cudaStream_t s2 = nullptr;
    static cudaEvent_t evFork = nullptr, evJoin = nullptr;
    if (s2 == nullptr) {
        cudaStreamCreateWithFlags(&s2, cudaStreamNonBlocking);
        cudaEventCreateWithFlags(&evFork, cudaEventDisableTiming);
        cudaEventCreateWithFlags(&evJoin, cudaEventDisableTiming);
    }

    const int write_keep = (out_size >= TOK * CDIM + BSZ * KEEP) ? 1 : 0;

    /* fork: exact fp32 top-k chain (reads only raw inputs) */
    cudaEventRecord(evFork, 0);
    cudaStreamWaitEvent(s2, evFork, 0);
    topk_qc  <<<dim3(BSZ, 12), 256, 0, s2>>>(x, qkv_w);
    topk_u   <<<dim3(BSZ, NH), 256, 0, s2>>>(qkv_w);
    topk_wt  <<<dim3(BSZ, (SEQ + 7) / 8), 256, 0, s2>>>(x);
    topk_emit<<<BSZ, 256, 0, s2>>>(out + (size_t)TOK * CDIM, write_keep);
    cudaEventRecord(evJoin, s2);

    /* main pipeline */
    split_all_kernel<<<(NSPLIT + 255)/256, 256>>>(x, qkv_w, proj_w);

    hmma_gemm<<<dim3(3*CDIM/NT, (TOK + MT - 1)/MT), 256, GEMM_SMEM>>>(0, nullptr, nullptr);

    fused_attn<<<BH, 256, FSMEM>>>();

    hmma_gemm<<<dim3(CDIM/NT, (TOK + MT - 1)/MT), 256, GEMM_SMEM>>>(1, proj_b, out);

    cudaStreamWaitEvent(0, evJoin, 0);
}

// round 16
// speedup vs baseline: 1.0874x; 1.0874x over previous
#include <cuda_runtime.h>
#include <cuda_bf16.h>
#include <math.h>
#include <stdint.h>

#define BSZ   64
#define SEQ   197
#define CDIM  768
#define NH    12
#define HD    64
#define KEEP  160
#define SCALEF 0.125f

#define BH   (BSZ*NH)
#define TOK  (BSZ*SEQ)

#define SEQP   228   /* global V^T pitch (u32 elems) */

/* ---------------- scratch (device globals; no allocs allowed) ------ */
__device__ __nv_bfloat16 g_qh[BH*SEQ*HD], g_ql[BH*SEQ*HD];
__device__ __nv_bfloat16 g_kh[BH*SEQ*HD], g_kl[BH*SEQ*HD];
__device__ uint32_t      g_vt[BH*HD*SEQP];

__device__ __nv_bfloat16 g_xh[TOK*CDIM],  g_xl[TOK*CDIM];
__device__ __nv_bfloat16 g_wqh[3*CDIM*CDIM], g_wql[3*CDIM*CDIM];
__device__ __nv_bfloat16 g_wph[CDIM*CDIM],   g_wpl[CDIM*CDIM];
__device__ __nv_bfloat16 g_cth[TOK*CDIM], g_ctl[TOK*CDIM];

/* top-k staging */
__device__ float g_qc[BSZ*CDIM];
__device__ float g_u [BSZ*NH*CDIM];
__device__ float g_wt[BSZ*SEQ];

/* ---------------- helpers ------------------------------------------ */
__device__ __forceinline__ uint32_t pack_hi_lo(float v0, float v1, uint32_t* lo)
{
    __nv_bfloat16 h0 = __float2bfloat16(v0);
    __nv_bfloat16 h1 = __float2bfloat16(v1);
    __nv_bfloat16 l0 = __float2bfloat16(v0 - __bfloat162float(h0));
    __nv_bfloat16 l1 = __float2bfloat16(v1 - __bfloat162float(h1));
    uint32_t hi = ((uint32_t)__bfloat16_as_ushort(h1) << 16) | __bfloat16_as_ushort(h0);
    *lo         = ((uint32_t)__bfloat16_as_ushort(l1) << 16) | __bfloat16_as_ushort(l0);
    return hi;
}
__device__ __forceinline__ uint32_t pack_v(float v)
{
    __nv_bfloat16 h = __float2bfloat16(v);
    __nv_bfloat16 l = __float2bfloat16(v - __bfloat162float(h));
    return (uint32_t)__bfloat16_as_ushort(h) | ((uint32_t)__bfloat16_as_ushort(l) << 16);
}

#define CP_ASYNC16(dst, src) \
    asm volatile("cp.async.cg.shared.global [%0], [%1], 16;" :: "r"(dst), "l"(src))
#define CP_COMMIT() asm volatile("cp.async.commit_group;" ::: "memory")
#define CP_WAIT(n)  asm volatile("cp.async.wait_group %0;" :: "n"(n) : "memory")

__device__ __forceinline__ void ldsm4(uint32_t* r, const void* p)
{
    uint32_t a = (uint32_t)__cvta_generic_to_shared(p);
    asm volatile("ldmatrix.sync.aligned.m8n8.x4.shared.b16 {%0,%1,%2,%3}, [%4];"
                 : "=r"(r[0]), "=r"(r[1]), "=r"(r[2]), "=r"(r[3]) : "r"(a));
}

/* ---------------- merged split fp32 -> bf16 hi/lo (4x vectorized) -- */
#define NX  (TOK*CDIM)
#define NWQ (3*CDIM*CDIM)
#define NWP (CDIM*CDIM)
#define NSPLIT (NX + NWQ + NWP)
#define NSPLIT4 (NSPLIT/4)

__global__ void split_all_kernel(const float* __restrict__ x,
                                 const float* __restrict__ wq,
                                 const float* __restrict__ wp)
{
    int i4 = blockIdx.x * 256 + threadIdx.x;
    if (i4 >= NSPLIT4) return;
    int i = i4 * 4;
    const float* s;
    __nv_bfloat16 *hi, *lo;
    int j;
    if (i < NX)            { s = x;  hi = g_xh;  lo = g_xl;  j = i; }
    else if (i < NX + NWQ) { s = wq; hi = g_wqh; lo = g_wql; j = i - NX; }
    else                   { s = wp; hi = g_wph; lo = g_wpl; j = i - NX - NWQ; }

    const float4 v = *reinterpret_cast<const float4*>(s + j);
    uint32_t l0, h0 = pack_hi_lo(v.x, v.y, &l0);
    uint32_t l1, h1 = pack_hi_lo(v.z, v.w, &l1);
    *reinterpret_cast<uint2*>(hi + j) = make_uint2(h0, h1);
    *reinterpret_cast<uint2*>(lo + j) = make_uint2(l0, l1);
}

/* ---------------- HMMA GEMM: 128x128 tile, occ 2 (R13 shape) ------- */
#define MT 128
#define NT 128
#define KPAN 32
#define SPAD 40
#define TILEB (128*SPAD*2)
#define STAGEB (4*TILEB)
#define GEMM_SMEM (2*STAGEB)   /* 81920 B */

__device__ __forceinline__ void mma16816(float* c, const uint32_t* a,
                                         uint32_t b0, uint32_t b1)
{
    asm volatile(
        "mma.sync.aligned.m16n8k16.row.col.f32.bf16.bf16.f32 "
        "{%0,%1,%2,%3}, {%4,%5,%6,%7}, {%8,%9}, {%0,%1,%2,%3};"
        : "+f"(c[0]), "+f"(c[1]), "+f"(c[2]), "+f"(c[3])
        : "r"(a[0]), "r"(a[1]), "r"(a[2]), "r"(a[3]), "r"(b0), "r"(b1));
}

__device__ __forceinline__ void stage_async(uint32_t sbase,
        const __nv_bfloat16* __restrict__ g, int row0, int rowmax, int kb, int t)
{
#pragma unroll
    for (int i = 0; i < 2; i++) {
        const int idx = t + i * 256;
        const int row = idx >> 2;
        const int c8  = (idx & 3) * 8;
        int gr = row0 + row; if (gr > rowmax) gr = rowmax;
        CP_ASYNC16(sbase + (uint32_t)(row * SPAD + c8) * 2,
                   g + (size_t)gr * CDIM + kb + c8);
    }
}

/* 3-pass split-bf16 MMA over one staged panel via LDSM. */
__device__ __forceinline__ void panel_mma(
        const __nv_bfloat16* sAh, const __nv_bfloat16* sAl,
        const __nv_bfloat16* sBh, const __nv_bfloat16* sBl,
        int pitch, int wm, int wn, int nNi2, int lane, float acc[][8][4])
{
    const int lrA = lane & 15;
    const int lcA = (lane >> 4) << 3;
    const int lrB = ((lane >> 4) << 3) | (lane & 7);
    const int lcB = lane & 8;

#pragma unroll
    for (int ks = 0; ks < 2; ks++) {
        const int ko = ks * 16;
        uint32_t ah[2][4], al[2][4];
#pragma unroll
        for (int mi = 0; mi < 2; mi++) {
            ldsm4(ah[mi], &sAh[(wm + mi * 16 + lrA) * pitch + ko + lcA]);
            ldsm4(al[mi], &sAl[(wm + mi * 16 + lrA) * pitch + ko + lcA]);
        }
#pragma unroll
        for (int ni2 = 0; ni2 < 4; ni2++) {
            if (ni2 >= nNi2) break;
            uint32_t bh4[4], bl4[4];
            ldsm4(bh4, &sBh[(wn + ni2 * 16 + lrB) * pitch + ko + lcB]);
            ldsm4(bl4, &sBl[(wn + ni2 * 16 + lrB) * pitch + ko + lcB]);
#pragma unroll
            for (int mi = 0; mi < 2; mi++) {
                mma16816(acc[mi][2*ni2    ], ah[mi], bh4[0], bh4[1]);
                mma16816(acc[mi][2*ni2    ], ah[mi], bl4[0], bl4[1]);
                mma16816(acc[mi][2*ni2    ], al[mi], bh4[0], bh4[1]);
                mma16816(acc[mi][2*ni2 + 1], ah[mi], bh4[2], bh4[3]);
                mma16816(acc[mi][2*ni2 + 1], ah[mi], bl4[2], bl4[3]);
                mma16816(acc[mi][2*ni2 + 1], al[mi], bh4[2], bh4[3]);
            }
        }
    }
}

__global__ __launch_bounds__(256, 2) void hmma_gemm(int mode,
        const float* __restrict__ bias, float* __restrict__ outp)
{
    extern __shared__ __align__(16) char dynsm[];
    const uint32_t sb = (uint32_t)__cvta_generic_to_shared(dynsm);

    const int t    = threadIdx.x;
    const int wid  = t >> 5, lane = t & 31;
    const int gq   = lane >> 2, tig = lane & 3;
    const int wm   = (wid & 3) * 32;
    const int wn   = (wid >> 2) * 64;
    const int m0   = blockIdx.y * MT;
    const int n0   = blockIdx.x * NT;

    const __nv_bfloat16 *Ah, *Al, *Bh, *Bl;
    int brmax;
    if (mode == 0) { Ah = g_xh;  Al = g_xl;  Bh = g_wqh; Bl = g_wql; brmax = 3*CDIM - 1; }
    else           { Ah = g_cth; Al = g_ctl; Bh = g_wph; Bl = g_wpl; brmax = CDIM - 1;   }

    float acc[2][8][4];
#pragma unroll
    for (int mi = 0; mi < 2; mi++)
#pragma unroll
        for (int ni = 0; ni < 8; ni++)
#pragma unroll
            for (int r = 0; r < 4; r++) acc[mi][ni][r] = 0.f;

    stage_async(sb + 0*TILEB, Ah, m0, TOK - 1, 0, t);
    stage_async(sb + 1*TILEB, Al, m0, TOK - 1, 0, t);
    stage_async(sb + 2*TILEB, Bh, n0, brmax,   0, t);
    stage_async(sb + 3*TILEB, Bl, n0, brmax,   0, t);
    CP_COMMIT();

    const int NP = CDIM / KPAN;
    for (int p = 0; p < NP; p++) {
        if (p + 1 < NP) {
            const uint32_t nb = sb + ((p + 1) & 1) * STAGEB;
            const int kb = (p + 1) * KPAN;
            stage_async(nb + 0*TILEB, Ah, m0, TOK - 1, kb, t);
            stage_async(nb + 1*TILEB, Al, m0, TOK - 1, kb, t);
            stage_async(nb + 2*TILEB, Bh, n0, brmax,   kb, t);
            stage_async(nb + 3*TILEB, Bl, n0, brmax,   kb, t);
            CP_COMMIT();
            CP_WAIT(1);
        } else {
            CP_WAIT(0);
        }
        __syncthreads();

        const char* cbuf = dynsm + (p & 1) * STAGEB;
        panel_mma((const __nv_bfloat16*)(cbuf + 0*TILEB),
                  (const __nv_bfloat16*)(cbuf + 1*TILEB),
                  (const __nv_bfloat16*)(cbuf + 2*TILEB),
                  (const __nv_bfloat16*)(cbuf + 3*TILEB),
                  SPAD, wm, wn, 4, lane, acc);
        __syncthreads();
    }

#pragma unroll
    for (int mi = 0; mi < 2; mi++) {
#pragma unroll
        for (int h2 = 0; h2 < 2; h2++) {
            const int m = m0 + wm + mi * 16 + gq + h2 * 8;
            if (m >= TOK) continue;
#pragma unroll
            for (int ni = 0; ni < 8; ni++) {
                const int col = n0 + wn + ni * 8 + 2 * tig;
                const float v0 = acc[mi][ni][h2 * 2 + 0];
                const float v1 = acc[mi][ni][h2 * 2 + 1];
                if (mode == 1) {
                    float2 o = make_float2(v0 + bias[col], v1 + bias[col + 1]);
                    *reinterpret_cast<float2*>(&outp[(size_t)m * CDIM + col]) = o;
                } else {
                    const int s  = col / CDIM;
                    const int rm = col % CDIM;
                    const int h  = rm / HD, dd = rm % HD;
                    const int bidx = m / SEQ, n = m % SEQ;
                    if (s == 2) {
                        const size_t vo = ((size_t)(bidx * NH + h) * HD + dd) * SEQP + n;
                        g_vt[vo]        = pack_v(v0);
                        g_vt[vo + SEQP] = pack_v(v1);
                    } else {
                        const size_t off = ((size_t)(bidx * NH + h) * SEQ + n) * HD + dd;
                        uint32_t lo, hi = pack_hi_lo(v0, v1, &lo);
                        __nv_bfloat16 *dh = (s == 0) ? g_qh : g_kh;
                        __nv_bfloat16 *dl = (s == 0) ? g_ql : g_kl;
                        *reinterpret_cast<uint32_t*>(&dh[off]) = hi;
                        *reinterpret_cast<uint32_t*>(&dl[off]) = lo;
                    }
                }
            }
        }
    }
}

/* ---------------- fused scores + softmax + PV (persistent per bh) -- */
#define FPITCH 232
#define QPITCH 72
#define SP_OFF 0
#define Q_OFF  59392
#define K_OFF  77824
#define V_OFF  151552
#define FSMEM  210944

__global__ __launch_bounds__(256, 1) void fused_attn()
{
    extern __shared__ __align__(16) char fsm[];
    float*         S  = (float*)(fsm + SP_OFF);
    __nv_bfloat16* Ph = (__nv_bfloat16*)(fsm + SP_OFF);
    __nv_bfloat16* Pl = (__nv_bfloat16*)(fsm + SP_OFF + 64*FPITCH*2);
    __nv_bfloat16* Qh = (__nv_bfloat16*)(fsm + Q_OFF);
    __nv_bfloat16* Ql = Qh + 64*QPITCH;
    __nv_bfloat16* Kh = (__nv_bfloat16*)(fsm + K_OFF);
    __nv_bfloat16* Kl = Kh + 256*QPITCH;
    __nv_bfloat16* Vh = (__nv_bfloat16*)(fsm + V_OFF);
    __nv_bfloat16* Vl = Vh + 64*FPITCH;

    const int bh   = blockIdx.x;
    const int b    = bh / NH, h = bh % NH;
    const int t    = threadIdx.x;
    const int lane = t & 31;
    const int w    = t >> 5;
    const int gq   = lane >> 2, tig = lane & 3;
    const int lrA  = lane & 15;
    const int lcA  = (lane >> 4) << 3;
    const int lrB  = ((lane >> 4) << 3) | (lane & 7);
    const int lcB  = lane & 8;

    const size_t base = (size_t)bh * SEQ * HD;

    /* stage K once */
#pragma unroll
    for (int i = 0; i < 8; i++) {
        const int idx = t + i * 256;
        const int row = idx >> 3;
        const int c8  = (idx & 7) * 8;
        int gr = row; if (gr > SEQ - 1) gr = SEQ - 1;
        *reinterpret_cast<uint4*>(&Kh[row * QPITCH + c8]) =
            *reinterpret_cast<const uint4*>(&g_kh[base + (size_t)gr * HD + c8]);
        *reinterpret_cast<uint4*>(&Kl[row * QPITCH + c8]) =
            *reinterpret_cast<const uint4*>(&g_kl[base + (size_t)gr * HD + c8]);
    }
    /* stage V^T once */
    const uint32_t* vt = g_vt + (size_t)bh * HD * SEQP;
#pragma unroll
    for (int dd = 0; dd < 8; dd++) {
        const int d = w * 8 + dd;
#pragma unroll
        for (int i = 0; i < 8; i++) {
            const int n = lane + i * 32;
            if (n < FPITCH) {
                uint32_t p = (n < SEQP) ? vt[d * SEQP + n] : 0u;
                Vh[d * FPITCH + n] = __ushort_as_bfloat16((unsigned short)(p & 0xffffu));
                Vl[d * FPITCH + n] = __ushort_as_bfloat16((unsigned short)(p >> 16));
            }
        }
    }

    for (int qt = 0; qt < 4; qt++) {
        const int q0 = qt * 64;

#pragma unroll
        for (int i = 0; i < 2; i++) {
            const int idx = t + i * 256;
            const int row = idx >> 3;
            const int c8  = (idx & 7) * 8;
            int gr = q0 + row; if (gr > SEQ - 1) gr = SEQ - 1;
            *reinterpret_cast<uint4*>(&Qh[row * QPITCH + c8]) =
                *reinterpret_cast<const uint4*>(&g_qh[base + (size_t)gr * HD + c8]);
            *reinterpret_cast<uint4*>(&Ql[row * QPITCH + c8]) =
                *reinterpret_cast<const uint4*>(&g_ql[base + (size_t)gr * HD + c8]);
        }
        __syncthreads();

        /* phase 1: S = Q K^T */
        {
            const int wm = (w & 1) * 32;
            const int wn = (w >> 1) * 64;
            float sacc[2][8][4];
#pragma unroll
            for (int mi = 0; mi < 2; mi++)
#pragma unroll
                for (int ni = 0; ni < 8; ni++)
#pragma unroll
                    for (int r = 0; r < 4; r++) sacc[mi][ni][r] = 0.f;

#pragma unroll
            for (int ks = 0; ks < 4; ks++) {
                const int ko = ks * 16;
                uint32_t ah[2][4], al[2][4];
#pragma unroll
                for (int mi = 0; mi < 2; mi++) {
                    ldsm4(ah[mi], &Qh[(wm + mi * 16 + lrA) * QPITCH + ko + lcA]);
                    ldsm4(al[mi], &Ql[(wm + mi * 16 + lrA) * QPITCH + ko + lcA]);
                }
#pragma unroll
                for (int ni2 = 0; ni2 < 4; ni2++) {
                    uint32_t bh4[4], bl4[4];
                    ldsm4(bh4, &Kh[(wn + ni2 * 16 + lrB) * QPITCH + ko + lcB]);
                    ldsm4(bl4, &Kl[(wn + ni2 * 16 + lrB) * QPITCH + ko + lcB]);
#pragma unroll
                    for (int mi = 0; mi < 2; mi++) {
                        mma16816(sacc[mi][2*ni2    ], ah[mi], bh4[0], bh4[1]);
                        mma16816(sacc[mi][2*ni2    ], ah[mi], bl4[0], bl4[1]);
                        mma16816(sacc[mi][2*ni2    ], al[mi], bh4[0], bh4[1]);
                        mma16816(sacc[mi][2*ni2 + 1], ah[mi], bh4[2], bh4[3]);
                        mma16816(sacc[mi][2*ni2 + 1], ah[mi], bl4[2], bl4[3]);
                        mma16816(sacc[mi][2*ni2 + 1], al[mi], bh4[2], bh4[3]);
                    }
                }
            }
#pragma unroll
            for (int mi = 0; mi < 2; mi++)
#pragma unroll
                for (int h2 = 0; h2 < 2; h2++) {
                    const int row = wm + mi * 16 + gq + h2 * 8;
#pragma unroll
                    for (int ni = 0; ni < 8; ni++) {
                        const int col = wn + ni * 8 + 2 * tig;
                        if (col + 1 < FPITCH) {
                            S[row * FPITCH + col]     = sacc[mi][ni][h2*2+0] * SCALEF;
                            S[row * FPITCH + col + 1] = sacc[mi][ni][h2*2+1] * SCALEF;
                        }
                    }
                }
        }
        __syncthreads();

        /* phase 2: softmax */
        float pv[8][8];
#pragma unroll
        for (int r8 = 0; r8 < 8; r8++) {
            const int sr = w * 8 + r8;
            float mx = -1e30f;
#pragma unroll
            for (int i = 0; i < 8; i++) {
                const int c = lane + i * 32;
                float v = (c < SEQ) ? S[sr * FPITCH + c] : -1e30f;
                pv[r8][i] = v;
                mx = fmaxf(mx, v);
            }
#pragma unroll
            for (int off = 16; off > 0; off >>= 1)
                mx = fmaxf(mx, __shfl_xor_sync(0xffffffffu, mx, off));
            float s = 0.f;
#pragma unroll
            for (int i = 0; i < 8; i++) {
                const int c = lane + i * 32;
                const float e = (c < SEQ) ? __expf(pv[r8][i] - mx) : 0.f;
                pv[r8][i] = e;
                s += e;
            }
#pragma unroll
            for (int off = 16; off > 0; off >>= 1)
                s += __shfl_xor_sync(0xffffffffu, s, off);
            const float inv = 1.f / s;
#pragma unroll
            for (int i = 0; i < 8; i++) pv[r8][i] *= inv;
        }
        __syncthreads();
#pragma unroll
        for (int r8 = 0; r8 < 8; r8++) {
            const int sr = w * 8 + r8;
#pragma unroll
            for (int i = 0; i < 8; i++) {
                const int c = lane + i * 32;
                if (c < FPITCH) {
                    const float p = pv[r8][i];
                    __nv_bfloat16 ph = __float2bfloat16(p);
                    __nv_bfloat16 pl = __float2bfloat16(p - __bfloat162float(ph));
                    Ph[sr * FPITCH + c] = ph;
                    Pl[sr * FPITCH + c] = pl;
                }
            }
        }
        __syncthreads();

        /* phase 3: ctx = P @ V */
        {
            const int wm = (w & 1) * 32;
            const int wn = (w >> 1) * 16;
            float acc[2][2][4];
#pragma unroll
            for (int mi = 0; mi < 2; mi++)
#pragma unroll
                for (int ni = 0; ni < 2; ni++)
#pragma unroll
                    for (int r = 0; r < 4; r++) acc[mi][ni][r] = 0.f;

#pragma unroll 1
            for (int ks = 0; ks < 13; ks++) {
                const int ko = ks * 16;
                uint32_t ah[2][4], al[2][4];
#pragma unroll
                for (int mi = 0; mi < 2; mi++) {
                    ldsm4(ah[mi], &Ph[(wm + mi * 16 + lrA) * FPITCH + ko + lcA]);
                    ldsm4(al[mi], &Pl[(wm + mi * 16 + lrA) * FPITCH + ko + lcA]);
                }
                uint32_t bh4[4], bl4[4];
                ldsm4(bh4, &Vh[(wn + lrB) * FPITCH + ko + lcB]);
                ldsm4(bl4, &Vl[(wn + lrB) * FPITCH + ko + lcB]);
#pragma unroll
                for (int mi = 0; mi < 2; mi++) {
                    mma16816(acc[mi][0], ah[mi], bh4[0], bh4[1]);
                    mma16816(acc[mi][0], ah[mi], bl4[0], bl4[1]);
                    mma16816(acc[mi][0], al[mi], bh4[0], bh4[1]);
                    mma16816(acc[mi][1], ah[mi], bh4[2], bh4[3]);
                    mma16816(acc[mi][1], ah[mi], bl4[2], bl4[3]);
                    mma16816(acc[mi][1], al[mi], bh4[2], bh4[3]);
                }
            }

#pragma unroll
            for (int mi = 0; mi < 2; mi++)
#pragma unroll
                for (int h2 = 0; h2 < 2; h2++) {
                    const int r = q0 + wm + mi * 16 + gq + h2 * 8;
                    if (r >= SEQ) continue;
#pragma unroll
                    for (int ni = 0; ni < 2; ni++) {
                        const int col = wn + ni * 8 + 2 * tig;
                        const size_t off = (size_t)(b * SEQ + r) * CDIM + h * HD + col;
                        uint32_t lo, hi = pack_hi_lo(acc[mi][ni][h2*2+0], acc[mi][ni][h2*2+1], &lo);
                        *reinterpret_cast<uint32_t*>(&g_cth[off]) = hi;
                        *reinterpret_cast<uint32_t*>(&g_ctl[off]) = lo;
                    }
                }
        }
        __syncthreads();
    }
}

/* ---------------- top-k stages (exact fp32) ------------------------ */
__global__ __launch_bounds__(256) void topk_qc(const float* __restrict__ x,
                                               const float* __restrict__ w)
{
    __shared__ float xc[CDIM];
    const int b  = blockIdx.x;
    const int jt = blockIdx.y;
    const int t  = threadIdx.x;
    const int lane = t & 31, wrp = t >> 5;

    for (int i = t; i < CDIM; i += 256) xc[i] = x[(size_t)(b * SEQ) * CDIM + i];
    __syncthreads();

#pragma unroll
    for (int jj = 0; jj < 8; jj++) {
        const int j = jt * 64 + wrp * 8 + jj;
        const float* wr = w + (size_t)j * CDIM;
        float s = 0.f;
#pragma unroll
        for (int c4 = 0; c4 < 6; c4++) {
            const int c = (c4 * 32 + lane) * 4;
            const float4 wv = *reinterpret_cast<const float4*>(&wr[c]);
            s += wv.x * xc[c] + wv.y * xc[c+1] + wv.z * xc[c+2] + wv.w * xc[c+3];
        }
#pragma unroll
        for (int off = 16; off > 0; off >>= 1)
            s += __shfl_xor_sync(0xffffffffu, s, off);
        if (lane == 0) g_qc[b * CDIM + j] = s;
    }
}

__global__ __launch_bounds__(256) void topk_u(const float* __restrict__ w)
{
    __shared__ float qh[HD];
    const int b = blockIdx.x, h = blockIdx.y;
    const int t = threadIdx.x;
    if (t < HD) qh[t] = g_qc[b * CDIM + h * HD + t];
    __syncthreads();

    const float* wk = w + (size_t)(CDIM + h * HD) * CDIM;
#pragma unroll
    for (int cc = 0; cc < 3; cc++) {
        const int c = cc * 256 + t;
        float s = 0.f;
#pragma unroll 16
        for (int d = 0; d < HD; d++) s += wk[(size_t)d * CDIM + c] * qh[d];
        g_u[((size_t)b * NH + h) * CDIM + c] = s;
    }
}

__global__ __launch_bounds__(256) void topk_wt(const float* __restrict__ x)
{
    const int b = blockIdx.x;
    const int t = threadIdx.x;
    const int lane = t & 31, wrp = t >> 5;
    const int m = blockIdx.y * 8 + wrp;
    if (m >= SEQ) return;

    const float* xr = x + (size_t)(b * SEQ + m) * CDIM;
    float4 xv[6];
#pragma unroll
    for (int c4 = 0; c4 < 6; c4++)
        xv[c4] = *reinterpret_cast<const float4*>(&xr[(c4 * 32 + lane) * 4]);

    const float* ub = g_u + (size_t)b * NH * CDIM;
    float tot = 0.f;
#pragma unroll
    for (int h = 0; h < NH; h++) {
        const float* ur = ub + h * CDIM;
        float s = 0.f;
#pragma unroll
        for (int c4 = 0; c4 < 6; c4++) {
            const int c = (c4 * 32 + lane) * 4;
            const float4 uv = *reinterpret_cast<const float4*>(&ur[c]);
            s += uv.x * xv[c4].x + uv.y * xv[c4].y + uv.z * xv[c4].z + uv.w * xv[c4].w;
        }
#pragma unroll
        for (int off = 16; off > 0; off >>= 1)
            s += __shfl_xor_sync(0xffffffffu, s, off);
        tot += fabsf(s);
    }
    if (lane == 0) g_wt[b * SEQ + m] = tot;
}

__global__ __launch_bounds__(256) void topk_emit(float* __restrict__ out_keep,
                                                 int write_keep)
{
    __shared__ float wt[SEQ];
    __shared__ unsigned char keep[SEQ];
    const int b = blockIdx.x, t = threadIdx.x;

    if (t < SEQ) wt[t] = g_wt[b * SEQ + t];
    __syncthreads();
    if (t < SEQ) {
        const float wi = wt[t];
        int cnt = 0;
        for (int j = 0; j < SEQ; j++) {
            const float wj = wt[j];
            cnt += (wj > wi) || (wj == wi && j < t);
        }
        keep[t] = (cnt < KEEP) ? 1 : 0;
    }
    __syncthreads();
    if (write_keep && t < SEQ && keep[t]) {
        int pos = 0;
        for (int j = 0; j < t; j++) pos += keep[j];
        out_keep[b * KEEP + pos] = (float)t;
    }
}

/* ------------------------------------------------------------------ */
extern "C" void kernel_launch(void* const* d_in, const int* in_sizes, int n_in,
                              void* d_out, int out_size)
{
    const float* x      = (const float*)d_in[0];
    const float* qkv_w  = (const float*)d_in[1];
    const float* proj_w = (const float*)d_in[2];
    const float* proj_b = (const float*)d_in[3];
    float* out = (float*)d_out;

    cudaFuncSetAttribute(hmma_gemm,  cudaFuncAttributeMaxDynamicSharedMemorySize, GEMM_SMEM);
    cudaFuncSetAttribute(fused_attn, cudaFuncAttributeMaxDynamicSharedMemorySize, FSMEM);

    static cudaStream_t s2 = nullptr;
    static cudaEvent_t evFork = nullptr, evJoin = nullptr;
    if (s2 == nullptr) {
        cudaStreamCreateWithFlags(&s2, cudaStreamNonBlocking);
        cudaEventCreateWithFlags(&evFork, cudaEventDisableTiming);
        cudaEventCreateWithFlags(&evJoin, cudaEventDisableTiming);
    }

    const int write_keep = (out_size >= TOK * CDIM + BSZ * KEEP) ? 1 : 0;

    /* fork: exact fp32 top-k chain (reads only raw inputs) */
    cudaEventRecord(evFork, 0);
    cudaStreamWaitEvent(s2, evFork, 0);
    topk_qc  <<<dim3(BSZ, 12), 256, 0, s2>>>(x, qkv_w);
    topk_u   <<<dim3(BSZ, NH), 256, 0, s2>>>(qkv_w);
    topk_wt  <<<dim3(BSZ, (SEQ + 7) / 8), 256, 0, s2>>>(x);
    topk_emit<<<BSZ, 256, 0, s2>>>(out + (size_t)TOK * CDIM, write_keep);
    cudaEventRecord(evJoin, s2);

    /* main pipeline */
    split_all_kernel<<<(NSPLIT4 + 255)/256, 256>>>(x, qkv_w, proj_w);

    hmma_gemm<<<dim3(3*CDIM/NT, (TOK + MT - 1)/MT), 256, GEMM_SMEM>>>(0, nullptr, nullptr);

    fused_attn<<<BH, 256, FSMEM>>>();

    hmma_gemm<<<dim3(CDIM/NT, (TOK + MT - 1)/MT), 256, GEMM_SMEM>>>(1, proj_b, out);

    cudaStreamWaitEvent(0, evJoin, 0);
}

// round 17
// speedup vs baseline: 1.1104x; 1.0211x over previous
#include <cuda_runtime.h>
#include <cuda_bf16.h>
#include <math.h>
#include <stdint.h>

#define BSZ   64
#define SEQ   197
#define CDIM  768
#define NH    12
#define HD    64
#define KEEP  160
#define SCALEF 0.125f

#define BH   (BSZ*NH)
#define TOK  (BSZ*SEQ)

#define SEQP   228   /* global V^T pitch (u32 elems) */

/* ---------------- scratch (device globals; no allocs allowed) ------ */
__device__ __nv_bfloat16 g_qh[BH*SEQ*HD], g_ql[BH*SEQ*HD];
__device__ __nv_bfloat16 g_kh[BH*SEQ*HD], g_kl[BH*SEQ*HD];
__device__ uint32_t      g_vt[BH*HD*SEQP];

__device__ __nv_bfloat16 g_xh[TOK*CDIM],  g_xl[TOK*CDIM];
__device__ __nv_bfloat16 g_wqh[3*CDIM*CDIM], g_wql[3*CDIM*CDIM];
__device__ __nv_bfloat16 g_wph[CDIM*CDIM],   g_wpl[CDIM*CDIM];
__device__ __nv_bfloat16 g_cth[TOK*CDIM], g_ctl[TOK*CDIM];

/* top-k staging */
__device__ float g_qc[BSZ*CDIM];
__device__ float g_u [BSZ*NH*CDIM];
__device__ float g_wt[BSZ*SEQ];

/* ---------------- helpers ------------------------------------------ */
__device__ __forceinline__ uint32_t pack_hi_lo(float v0, float v1, uint32_t* lo)
{
    __nv_bfloat16 h0 = __float2bfloat16(v0);
    __nv_bfloat16 h1 = __float2bfloat16(v1);
    __nv_bfloat16 l0 = __float2bfloat16(v0 - __bfloat162float(h0));
    __nv_bfloat16 l1 = __float2bfloat16(v1 - __bfloat162float(h1));
    uint32_t hi = ((uint32_t)__bfloat16_as_ushort(h1) << 16) | __bfloat16_as_ushort(h0);
    *lo         = ((uint32_t)__bfloat16_as_ushort(l1) << 16) | __bfloat16_as_ushort(l0);
    return hi;
}
__device__ __forceinline__ uint32_t pack_v(float v)
{
    __nv_bfloat16 h = __float2bfloat16(v);
    __nv_bfloat16 l = __float2bfloat16(v - __bfloat162float(h));
    return (uint32_t)__bfloat16_as_ushort(h) | ((uint32_t)__bfloat16_as_ushort(l) << 16);
}

#define CP_ASYNC16(dst, src) \
    asm volatile("cp.async.cg.shared.global [%0], [%1], 16;" :: "r"(dst), "l"(src))
#define CP_COMMIT() asm volatile("cp.async.commit_group;" ::: "memory")
#define CP_WAIT(n)  asm volatile("cp.async.wait_group %0;" :: "n"(n) : "memory")

__device__ __forceinline__ void ldsm4(uint32_t* r, const void* p)
{
    uint32_t a = (uint32_t)__cvta_generic_to_shared(p);
    asm volatile("ldmatrix.sync.aligned.m8n8.x4.shared.b16 {%0,%1,%2,%3}, [%4];"
                 : "=r"(r[0]), "=r"(r[1]), "=r"(r[2]), "=r"(r[3]) : "r"(a));
}

/* ---------------- merged split fp32 -> bf16 hi/lo (4x vectorized) -- */
#define NX  (TOK*CDIM)
#define NWQ (3*CDIM*CDIM)
#define NWP (CDIM*CDIM)
#define NSPLIT (NX + NWQ + NWP)
#define NSPLIT4 (NSPLIT/4)

__global__ void split_all_kernel(const float* __restrict__ x,
                                 const float* __restrict__ wq,
                                 const float* __restrict__ wp)
{
    int i4 = blockIdx.x * 256 + threadIdx.x;
    if (i4 >= NSPLIT4) return;
    int i = i4 * 4;
    const float* s;
    __nv_bfloat16 *hi, *lo;
    int j;
    if (i < NX)            { s = x;  hi = g_xh;  lo = g_xl;  j = i; }
    else if (i < NX + NWQ) { s = wq; hi = g_wqh; lo = g_wql; j = i - NX; }
    else                   { s = wp; hi = g_wph; lo = g_wpl; j = i - NX - NWQ; }

    const float4 v = *reinterpret_cast<const float4*>(s + j);
    uint32_t l0, h0 = pack_hi_lo(v.x, v.y, &l0);
    uint32_t l1, h1 = pack_hi_lo(v.z, v.w, &l1);
    *reinterpret_cast<uint2*>(hi + j) = make_uint2(h0, h1);
    *reinterpret_cast<uint2*>(lo + j) = make_uint2(l0, l1);
}

/* ---------------- HMMA GEMM: 128x128 tile, occ 2 ------------------- */
#define MT 128
#define NT 128
#define KPAN 32
#define SPAD 40
#define TILEB (128*SPAD*2)
#define STAGEB (4*TILEB)
#define GEMM_SMEM (2*STAGEB)   /* 81920 B */

__device__ __forceinline__ void mma16816(float* c, const uint32_t* a,
                                         uint32_t b0, uint32_t b1)
{
    asm volatile(
        "mma.sync.aligned.m16n8k16.row.col.f32.bf16.bf16.f32 "
        "{%0,%1,%2,%3}, {%4,%5,%6,%7}, {%8,%9}, {%0,%1,%2,%3};"
        : "+f"(c[0]), "+f"(c[1]), "+f"(c[2]), "+f"(c[3])
        : "r"(a[0]), "r"(a[1]), "r"(a[2]), "r"(a[3]), "r"(b0), "r"(b1));
}

__device__ __forceinline__ void stage_async(uint32_t sbase,
        const __nv_bfloat16* __restrict__ g, int row0, int rowmax, int kb, int t)
{
#pragma unroll
    for (int i = 0; i < 2; i++) {
        const int idx = t + i * 256;
        const int row = idx >> 2;
        const int c8  = (idx & 3) * 8;
        int gr = row0 + row; if (gr > rowmax) gr = rowmax;
        CP_ASYNC16(sbase + (uint32_t)(row * SPAD + c8) * 2,
                   g + (size_t)gr * CDIM + kb + c8);
    }
}

/* 3-pass split-bf16 MMA over one staged panel via LDSM. */
__device__ __forceinline__ void panel_mma(
        const __nv_bfloat16* sAh, const __nv_bfloat16* sAl,
        const __nv_bfloat16* sBh, const __nv_bfloat16* sBl,
        int pitch, int wm, int wn, int nNi2, int lane, float acc[][8][4])
{
    const int lrA = lane & 15;
    const int lcA = (lane >> 4) << 3;
    const int lrB = ((lane >> 4) << 3) | (lane & 7);
    const int lcB = lane & 8;

#pragma unroll
    for (int ks = 0; ks < 2; ks++) {
        const int ko = ks * 16;
        uint32_t ah[2][4], al[2][4];
#pragma unroll
        for (int mi = 0; mi < 2; mi++) {
            ldsm4(ah[mi], &sAh[(wm + mi * 16 + lrA) * pitch + ko + lcA]);
            ldsm4(al[mi], &sAl[(wm + mi * 16 + lrA) * pitch + ko + lcA]);
        }
#pragma unroll
        for (int ni2 = 0; ni2 < 4; ni2++) {
            if (ni2 >= nNi2) break;
            uint32_t bh4[4], bl4[4];
            ldsm4(bh4, &sBh[(wn + ni2 * 16 + lrB) * pitch + ko + lcB]);
            ldsm4(bl4, &sBl[(wn + ni2 * 16 + lrB) * pitch + ko + lcB]);
#pragma unroll
            for (int mi = 0; mi < 2; mi++) {
                mma16816(acc[mi][2*ni2    ], ah[mi], bh4[0], bh4[1]);
                mma16816(acc[mi][2*ni2    ], ah[mi], bl4[0], bl4[1]);
                mma16816(acc[mi][2*ni2    ], al[mi], bh4[0], bh4[1]);
                mma16816(acc[mi][2*ni2 + 1], ah[mi], bh4[2], bh4[3]);
                mma16816(acc[mi][2*ni2 + 1], ah[mi], bl4[2], bl4[3]);
                mma16816(acc[mi][2*ni2 + 1], al[mi], bh4[2], bh4[3]);
            }
        }
    }
}

__global__ __launch_bounds__(256, 2) void hmma_gemm(int mode,
        const float* __restrict__ bias, float* __restrict__ outp)
{
    extern __shared__ __align__(16) char dynsm[];
    const uint32_t sb = (uint32_t)__cvta_generic_to_shared(dynsm);

    const int t    = threadIdx.x;
    const int wid  = t >> 5, lane = t & 31;
    const int gq   = lane >> 2, tig = lane & 3;
    const int wm   = (wid & 3) * 32;
    const int wn   = (wid >> 2) * 64;
    const int m0   = blockIdx.y * MT;
    const int n0   = blockIdx.x * NT;

    const __nv_bfloat16 *Ah, *Al, *Bh, *Bl;
    int brmax;
    if (mode == 0) { Ah = g_xh;  Al = g_xl;  Bh = g_wqh; Bl = g_wql; brmax = 3*CDIM - 1; }
    else           { Ah = g_cth; Al = g_ctl; Bh = g_wph; Bl = g_wpl; brmax = CDIM - 1;   }

    float acc[2][8][4];
#pragma unroll
    for (int mi = 0; mi < 2; mi++)
#pragma unroll
        for (int ni = 0; ni < 8; ni++)
#pragma unroll
            for (int r = 0; r < 4; r++) acc[mi][ni][r] = 0.f;

    stage_async(sb + 0*TILEB, Ah, m0, TOK - 1, 0, t);
    stage_async(sb + 1*TILEB, Al, m0, TOK - 1, 0, t);
    stage_async(sb + 2*TILEB, Bh, n0, brmax,   0, t);
    stage_async(sb + 3*TILEB, Bl, n0, brmax,   0, t);
    CP_COMMIT();

    const int NP = CDIM / KPAN;
    for (int p = 0; p < NP; p++) {
        if (p + 1 < NP) {
            const uint32_t nb = sb + ((p + 1) & 1) * STAGEB;
            const int kb = (p + 1) * KPAN;
            stage_async(nb + 0*TILEB, Ah, m0, TOK - 1, kb, t);
            stage_async(nb + 1*TILEB, Al, m0, TOK - 1, kb, t);
            stage_async(nb + 2*TILEB, Bh, n0, brmax,   kb, t);
            stage_async(nb + 3*TILEB, Bl, n0, brmax,   kb, t);
            CP_COMMIT();
            CP_WAIT(1);
        } else {
            CP_WAIT(0);
        }
        __syncthreads();

        const char* cbuf = dynsm + (p & 1) * STAGEB;
        panel_mma((const __nv_bfloat16*)(cbuf + 0*TILEB),
                  (const __nv_bfloat16*)(cbuf + 1*TILEB),
                  (const __nv_bfloat16*)(cbuf + 2*TILEB),
                  (const __nv_bfloat16*)(cbuf + 3*TILEB),
                  SPAD, wm, wn, 4, lane, acc);
        __syncthreads();
    }

#pragma unroll
    for (int mi = 0; mi < 2; mi++) {
#pragma unroll
        for (int h2 = 0; h2 < 2; h2++) {
            const int m = m0 + wm + mi * 16 + gq + h2 * 8;
            if (m >= TOK) continue;
#pragma unroll
            for (int ni = 0; ni < 8; ni++) {
                const int col = n0 + wn + ni * 8 + 2 * tig;
                const float v0 = acc[mi][ni][h2 * 2 + 0];
                const float v1 = acc[mi][ni][h2 * 2 + 1];
                if (mode == 1) {
                    float2 o = make_float2(v0 + bias[col], v1 + bias[col + 1]);
                    *reinterpret_cast<float2*>(&outp[(size_t)m * CDIM + col]) = o;
                } else {
                    const int s  = col / CDIM;
                    const int rm = col % CDIM;
                    const int h  = rm / HD, dd = rm % HD;
                    const int bidx = m / SEQ, n = m % SEQ;
                    if (s == 2) {
                        const size_t vo = ((size_t)(bidx * NH + h) * HD + dd) * SEQP + n;
                        g_vt[vo]        = pack_v(v0);
                        g_vt[vo + SEQP] = pack_v(v1);
                    } else {
                        const size_t off = ((size_t)(bidx * NH + h) * SEQ + n) * HD + dd;
                        uint32_t lo, hi = pack_hi_lo(v0, v1, &lo);
                        __nv_bfloat16 *dh = (s == 0) ? g_qh : g_kh;
                        __nv_bfloat16 *dl = (s == 0) ? g_ql : g_kl;
                        *reinterpret_cast<uint32_t*>(&dh[off]) = hi;
                        *reinterpret_cast<uint32_t*>(&dl[off]) = lo;
                    }
                }
            }
        }
    }
}

/* ---------------- fused scores + softmax + PV (persistent per bh) --
   Async staging: K + Q0 via cp.async overlapping V unpack; Q double-
   buffered with cp.async prefetch during compute.
   smem 229,376 B:
     [0, 59392)           S fp32 [64][232] (alias: P hi/lo bf16)
     [59392, 96256)       Q hi/lo x 2 buffers (18432 each)
     [96256, 169984)      K hi/lo [256][72]
     [169984, 229376)     V^T hi/lo [64][232]                           */
#define FPITCH 232
#define QPITCH 72
#define SP_OFF 0
#define Q_OFF  59392
#define QBUFB  18432
#define K_OFF  96256
#define V_OFF  169984
#define FSMEM  229376

__global__ __launch_bounds__(256, 1) void fused_attn()
{
    extern __shared__ __align__(16) char fsm[];
    float*         S  = (float*)(fsm + SP_OFF);
    __nv_bfloat16* Ph = (__nv_bfloat16*)(fsm + SP_OFF);
    __nv_bfloat16* Pl = (__nv_bfloat16*)(fsm + SP_OFF + 64*FPITCH*2);
    __nv_bfloat16* Kh = (__nv_bfloat16*)(fsm + K_OFF);
    __nv_bfloat16* Kl = Kh + 256*QPITCH;
    __nv_bfloat16* Vh = (__nv_bfloat16*)(fsm + V_OFF);
    __nv_bfloat16* Vl = Vh + 64*FPITCH;

    const uint32_t smb = (uint32_t)__cvta_generic_to_shared(fsm);

    const int bh   = blockIdx.x;
    const int b    = bh / NH, h = bh % NH;
    const int t    = threadIdx.x;
    const int lane = t & 31;
    const int w    = t >> 5;
    const int gq   = lane >> 2, tig = lane & 3;
    const int lrA  = lane & 15;
    const int lcA  = (lane >> 4) << 3;
    const int lrB  = ((lane >> 4) << 3) | (lane & 7);
    const int lcB  = lane & 8;

    const size_t base = (size_t)bh * SEQ * HD;

    /* async stage K (256 rows x 64 cols) */
#pragma unroll
    for (int i = 0; i < 8; i++) {
        const int idx = t + i * 256;
        const int row = idx >> 3;
        const int c8  = (idx & 7) * 8;
        int gr = row; if (gr > SEQ - 1) gr = SEQ - 1;
        CP_ASYNC16(smb + K_OFF + (uint32_t)(row * QPITCH + c8) * 2,
                   &g_kh[base + (size_t)gr * HD + c8]);
        CP_ASYNC16(smb + K_OFF + (uint32_t)(256 * QPITCH + row * QPITCH + c8) * 2,
                   &g_kl[base + (size_t)gr * HD + c8]);
    }
    /* async stage Q tile 0 into buffer 0 */
#pragma unroll
    for (int i = 0; i < 2; i++) {
        const int idx = t + i * 256;
        const int row = idx >> 3;
        const int c8  = (idx & 7) * 8;
        int gr = row; if (gr > SEQ - 1) gr = SEQ - 1;
        CP_ASYNC16(smb + Q_OFF + (uint32_t)(row * QPITCH + c8) * 2,
                   &g_qh[base + (size_t)gr * HD + c8]);
        CP_ASYNC16(smb + Q_OFF + (uint32_t)(64 * QPITCH + row * QPITCH + c8) * 2,
                   &g_ql[base + (size_t)gr * HD + c8]);
    }
    CP_COMMIT();

    /* V^T unpack (regular loads, overlaps the cp.async traffic) */
    const uint32_t* vt = g_vt + (size_t)bh * HD * SEQP;
#pragma unroll
    for (int dd = 0; dd < 8; dd++) {
        const int d = w * 8 + dd;
#pragma unroll
        for (int i = 0; i < 8; i++) {
            const int n = lane + i * 32;
            if (n < FPITCH) {
                uint32_t p = (n < SEQP) ? vt[d * SEQP + n] : 0u;
                Vh[d * FPITCH + n] = __ushort_as_bfloat16((unsigned short)(p & 0xffffu));
                Vl[d * FPITCH + n] = __ushort_as_bfloat16((unsigned short)(p >> 16));
            }
        }
    }
    CP_WAIT(0);
    __syncthreads();

    for (int qt = 0; qt < 4; qt++) {
        const int q0 = qt * 64;
        const __nv_bfloat16* Qh = (const __nv_bfloat16*)(fsm + Q_OFF + (qt & 1) * QBUFB);
        const __nv_bfloat16* Ql = Qh + 64 * QPITCH;

        /* prefetch next Q tile into the other buffer */
        if (qt < 3) {
            const uint32_t nqb = smb + Q_OFF + ((qt + 1) & 1) * QBUFB;
            const int nq0 = (qt + 1) * 64;
#pragma unroll
            for (int i = 0; i < 2; i++) {
                const int idx = t + i * 256;
                const int row = idx >> 3;
                const int c8  = (idx & 7) * 8;
                int gr = nq0 + row; if (gr > SEQ - 1) gr = SEQ - 1;
                CP_ASYNC16(nqb + (uint32_t)(row * QPITCH + c8) * 2,
                           &g_qh[base + (size_t)gr * HD + c8]);
                CP_ASYNC16(nqb + (uint32_t)(64 * QPITCH + row * QPITCH + c8) * 2,
                           &g_ql[base + (size_t)gr * HD + c8]);
            }
            CP_COMMIT();
        }

        /* phase 1: S = Q K^T */
        {
            const int wm = (w & 1) * 32;
            const int wn = (w >> 1) * 64;
            float sacc[2][8][4];
#pragma unroll
            for (int mi = 0; mi < 2; mi++)
#pragma unroll
                for (int ni = 0; ni < 8; ni++)
#pragma unroll
                    for (int r = 0; r < 4; r++) sacc[mi][ni][r] = 0.f;

#pragma unroll
            for (int ks = 0; ks < 4; ks++) {
                const int ko = ks * 16;
                uint32_t ah[2][4], al[2][4];
#pragma unroll
                for (int mi = 0; mi < 2; mi++) {
                    ldsm4(ah[mi], &Qh[(wm + mi * 16 + lrA) * QPITCH + ko + lcA]);
                    ldsm4(al[mi], &Ql[(wm + mi * 16 + lrA) * QPITCH + ko + lcA]);
                }
#pragma unroll
                for (int ni2 = 0; ni2 < 4; ni2++) {
                    uint32_t bh4[4], bl4[4];
                    ldsm4(bh4, &Kh[(wn + ni2 * 16 + lrB) * QPITCH + ko + lcB]);
                    ldsm4(bl4, &Kl[(wn + ni2 * 16 + lrB) * QPITCH + ko + lcB]);
#pragma unroll
                    for (int mi = 0; mi < 2; mi++) {
                        mma16816(sacc[mi][2*ni2    ], ah[mi], bh4[0], bh4[1]);
                        mma16816(sacc[mi][2*ni2    ], ah[mi], bl4[0], bl4[1]);
                        mma16816(sacc[mi][2*ni2    ], al[mi], bh4[0], bh4[1]);
                        mma16816(sacc[mi][2*ni2 + 1], ah[mi], bh4[2], bh4[3]);
                        mma16816(sacc[mi][2*ni2 + 1], ah[mi], bl4[2], bl4[3]);
                        mma16816(sacc[mi][2*ni2 + 1], al[mi], bh4[2], bh4[3]);
                    }
                }
            }
#pragma unroll
            for (int mi = 0; mi < 2; mi++)
#pragma unroll
                for (int h2 = 0; h2 < 2; h2++) {
                    const int row = wm + mi * 16 + gq + h2 * 8;
#pragma unroll
                    for (int ni = 0; ni < 8; ni++) {
                        const int col = wn + ni * 8 + 2 * tig;
                        if (col + 1 < FPITCH) {
                            S[row * FPITCH + col]     = sacc[mi][ni][h2*2+0] * SCALEF;
                            S[row * FPITCH + col + 1] = sacc[mi][ni][h2*2+1] * SCALEF;
                        }
                    }
                }
        }
        __syncthreads();

        /* phase 2: softmax */
        float pv[8][8];
#pragma unroll
        for (int r8 = 0; r8 < 8; r8++) {
            const int sr = w * 8 + r8;
            float mx = -1e30f;
#pragma unroll
            for (int i = 0; i < 8; i++) {
                const int c = lane + i * 32;
                float v = (c < SEQ) ? S[sr * FPITCH + c] : -1e30f;
                pv[r8][i] = v;
                mx = fmaxf(mx, v);
            }
#pragma unroll
            for (int off = 16; off > 0; off >>= 1)
                mx = fmaxf(mx, __shfl_xor_sync(0xffffffffu, mx, off));
            float s = 0.f;
#pragma unroll
            for (int i = 0; i < 8; i++) {
                const int c = lane + i * 32;
                const float e = (c < SEQ) ? __expf(pv[r8][i] - mx) : 0.f;
                pv[r8][i] = e;
                s += e;
            }
#pragma unroll
            for (int off = 16; off > 0; off >>= 1)
                s += __shfl_xor_sync(0xffffffffu, s, off);
            const float inv = 1.f / s;
#pragma unroll
            for (int i = 0; i < 8; i++) pv[r8][i] *= inv;
        }
        __syncthreads();
#pragma unroll
        for (int r8 = 0; r8 < 8; r8++) {
            const int sr = w * 8 + r8;
#pragma unroll
            for (int i = 0; i < 8; i++) {
                const int c = lane + i * 32;
                if (c < FPITCH) {
                    const float p = pv[r8][i];
                    __nv_bfloat16 ph = __float2bfloat16(p);
                    __nv_bfloat16 pl = __float2bfloat16(p - __bfloat162float(ph));
                    Ph[sr * FPITCH + c] = ph;
                    Pl[sr * FPITCH + c] = pl;
                }
            }
        }
        __syncthreads();

        /* phase 3: ctx = P @ V */
        {
            const int wm = (w & 1) * 32;
            const int wn = (w >> 1) * 16;
            float acc[2][2][4];
#pragma unroll
            for (int mi = 0; mi < 2; mi++)
#pragma unroll
                for (int ni = 0; ni < 2; ni++)
#pragma unroll
                    for (int r = 0; r < 4; r++) acc[mi][ni][r] = 0.f;

#pragma unroll 1
            for (int ks = 0; ks < 13; ks++) {
                const int ko = ks * 16;
                uint32_t ah[2][4], al[2][4];
#pragma unroll
                for (int mi = 0; mi < 2; mi++) {
                    ldsm4(ah[mi], &Ph[(wm + mi * 16 + lrA) * FPITCH + ko + lcA]);
                    ldsm4(al[mi], &Pl[(wm + mi * 16 + lrA) * FPITCH + ko + lcA]);
                }
                uint32_t bh4[4], bl4[4];
                ldsm4(bh4, &Vh[(wn + lrB) * FPITCH + ko + lcB]);
                ldsm4(bl4, &Vl[(wn + lrB) * FPITCH + ko + lcB]);
#pragma unroll
                for (int mi = 0; mi < 2; mi++) {
                    mma16816(acc[mi][0], ah[mi], bh4[0], bh4[1]);
                    mma16816(acc[mi][0], ah[mi], bl4[0], bl4[1]);
                    mma16816(acc[mi][0], al[mi], bh4[0], bh4[1]);
                    mma16816(acc[mi][1], ah[mi], bh4[2], bh4[3]);
                    mma16816(acc[mi][1], ah[mi], bl4[2], bl4[3]);
                    mma16816(acc[mi][1], al[mi], bh4[2], bh4[3]);
                }
            }

#pragma unroll
            for (int mi = 0; mi < 2; mi++)
#pragma unroll
                for (int h2 = 0; h2 < 2; h2++) {
                    const int r = q0 + wm + mi * 16 + gq + h2 * 8;
                    if (r >= SEQ) continue;
#pragma unroll
                    for (int ni = 0; ni < 2; ni++) {
                        const int col = wn + ni * 8 + 2 * tig;
                        const size_t off = (size_t)(b * SEQ + r) * CDIM + h * HD + col;
                        uint32_t lo, hi = pack_hi_lo(acc[mi][ni][h2*2+0], acc[mi][ni][h2*2+1], &lo);
                        *reinterpret_cast<uint32_t*>(&g_cth[off]) = hi;
                        *reinterpret_cast<uint32_t*>(&g_ctl[off]) = lo;
                    }
                }
        }
        if (qt < 3) CP_WAIT(0);   /* next Q tile landed */
        __syncthreads();          /* P reads done; Q buffer swap safe */
    }
}

/* ---------------- top-k stages (exact fp32) ------------------------ */
__global__ __launch_bounds__(256) void topk_qc(const float* __restrict__ x,
                                               const float* __restrict__ w)
{
    __shared__ float xc[CDIM];
    const int b  = blockIdx.x;
    const int jt = blockIdx.y;
    const int t  = threadIdx.x;
    const int lane = t & 31, wrp = t >> 5;

    for (int i = t; i < CDIM; i += 256) xc[i] = x[(size_t)(b * SEQ) * CDIM + i];
    __syncthreads();

#pragma unroll
    for (int jj = 0; jj < 8; jj++) {
        const int j = jt * 64 + wrp * 8 + jj;
        const float* wr = w + (size_t)j * CDIM;
        float s = 0.f;
#pragma unroll
        for (int c4 = 0; c4 < 6; c4++) {
            const int c = (c4 * 32 + lane) * 4;
            const float4 wv = *reinterpret_cast<const float4*>(&wr[c]);
            s += wv.x * xc[c] + wv.y * xc[c+1] + wv.z * xc[c+2] + wv.w * xc[c+3];
        }
#pragma unroll
        for (int off = 16; off > 0; off >>= 1)
            s += __shfl_xor_sync(0xffffffffu, s, off);
        if (lane == 0) g_qc[b * CDIM + j] = s;
    }
}

__global__ __launch_bounds__(256) void topk_u(const float* __restrict__ w)
{
    __shared__ float qh[HD];
    const int b = blockIdx.x, h = blockIdx.y;
    const int t = threadIdx.x;
    if (t < HD) qh[t] = g_qc[b * CDIM + h * HD + t];
    __syncthreads();

    const float* wk = w + (size_t)(CDIM + h * HD) * CDIM;
#pragma unroll
    for (int cc = 0; cc < 3; cc++) {
        const int c = cc * 256 + t;
        float s = 0.f;
#pragma unroll 16
        for (int d = 0; d < HD; d++) s += wk[(size_t)d * CDIM + c] * qh[d];
        g_u[((size_t)b * NH + h) * CDIM + c] = s;
    }
}

__global__ __launch_bounds__(256) void topk_wt(const float* __restrict__ x)
{
    const int b = blockIdx.x;
    const int t = threadIdx.x;
    const int lane = t & 31, wrp = t >> 5;
    const int m = blockIdx.y * 8 + wrp;
    if (m >= SEQ) return;

    const float* xr = x + (size_t)(b * SEQ + m) * CDIM;
    float4 xv[6];
#pragma unroll
    for (int c4 = 0; c4 < 6; c4++)
        xv[c4] = *reinterpret_cast<const float4*>(&xr[(c4 * 32 + lane) * 4]);

    const float* ub = g_u + (size_t)b * NH * CDIM;
    float tot = 0.f;
#pragma unroll
    for (int h = 0; h < NH; h++) {
        const float* ur = ub + h * CDIM;
        float s = 0.f;
#pragma unroll
        for (int c4 = 0; c4 < 6; c4++) {
            const int c = (c4 * 32 + lane) * 4;
            const float4 uv = *reinterpret_cast<const float4*>(&ur[c]);
            s += uv.x * xv[c4].x + uv.y * xv[c4].y + uv.z * xv[c4].z + uv.w * xv[c4].w;
        }
#pragma unroll
        for (int off = 16; off > 0; off >>= 1)
            s += __shfl_xor_sync(0xffffffffu, s, off);
        tot += fabsf(s);
    }
    if (lane == 0) g_wt[b * SEQ + m] = tot;
}

__global__ __launch_bounds__(256) void topk_emit(float* __restrict__ out_keep,
                                                 int write_keep)
{
    __shared__ float wt[SEQ];
    __shared__ unsigned char keep[SEQ];
    const int b = blockIdx.x, t = threadIdx.x;

    if (t < SEQ) wt[t] = g_wt[b * SEQ + t];
    __syncthreads();
    if (t < SEQ) {
        const float wi = wt[t];
        int cnt = 0;
        for (int j = 0; j < SEQ; j++) {
            const float wj = wt[j];
            cnt += (wj > wi) || (wj == wi && j < t);
        }
        keep[t] = (cnt < KEEP) ? 1 : 0;
    }
    __syncthreads();
    if (write_keep && t < SEQ && keep[t]) {
        int pos = 0;
        for (int j = 0; j < t; j++) pos += keep[j];
        out_keep[b * KEEP + pos] = (float)t;
    }
}

/* ------------------------------------------------------------------ */
extern "C" void kernel_launch(void* const* d_in, const int* in_sizes, int n_in,
                              void* d_out, int out_size)
{
    const float* x      = (const float*)d_in[0];
    const float* qkv_w  = (const float*)d_in[1];
    const float* proj_w = (const float*)d_in[2];
    const float* proj_b = (const float*)d_in[3];
    float* out = (float*)d_out;

    cudaFuncSetAttribute(hmma_gemm,  cudaFuncAttributeMaxDynamicSharedMemorySize, GEMM_SMEM);
    cudaFuncSetAttribute(fused_attn, cudaFuncAttributeMaxDynamicSharedMemorySize, FSMEM);

    static cudaStream_t s2 = nullptr;
    static cudaEvent_t evFork = nullptr, evJoin = nullptr;
    if (s2 == nullptr) {
        cudaStreamCreateWithFlags(&s2, cudaStreamNonBlocking);
        cudaEventCreateWithFlags(&evFork, cudaEventDisableTiming);
        cudaEventCreateWithFlags(&evJoin, cudaEventDisableTiming);
    }

    const int write_keep = (out_size >= TOK * CDIM + BSZ * KEEP) ? 1 : 0;

    /* fork: exact fp32 top-k chain (reads only raw inputs) */
    cudaEventRecord(evFork, 0);
    cudaStreamWaitEvent(s2, evFork, 0);
    topk_qc  <<<dim3(BSZ, 12), 256, 0, s2>>>(x, qkv_w);
    topk_u   <<<dim3(BSZ, NH), 256, 0, s2>>>(qkv_w);
    topk_wt  <<<dim3(BSZ, (SEQ + 7) / 8), 256, 0, s2>>>(x);
    topk_emit<<<BSZ, 256, 0, s2>>>(out + (size_t)TOK * CDIM, write_keep);
    cudaEventRecord(evJoin, s2);

    /* main pipeline */
    split_all_kernel<<<(NSPLIT4 + 255)/256, 256>>>(x, qkv_w, proj_w);

    hmma_gemm<<<dim3(3*CDIM/NT, (TOK + MT - 1)/MT), 256, GEMM_SMEM>>>(0, nullptr, nullptr);

    fused_attn<<<BH, 256, FSMEM>>>();

    hmma_gemm<<<dim3(CDIM/NT, (TOK + MT - 1)/MT), 256, GEMM_SMEM>>>(1, proj_b, out);

    cudaStreamWaitEvent(0, evJoin, 0);
}